// round 3
// baseline (speedup 1.0000x reference)
#include <cuda_runtime.h>
#include <math_constants.h>

namespace {
constexpr int B_   = 32;
constexpr int P_   = 197;
constexpr int D_   = 768;
constexpr int H_   = 12;
constexpr int HD_  = 64;
constexpr int PPR  = 49;    // rep tokens per reference sample
constexpr int NREF = 16;    // int(B * 0.5)
constexpr int NF   = 784;   // NREF * PPR
constexpr int TK   = 8;     // top-k
constexpr int PT   = 4;     // query rows per block
constexpr int NT   = (P_ + PT - 1) / PT;  // 50
constexpr float NEGF = -1e30f;
}

// scratch (device globals; no allocation allowed)
__device__ float g_qh[B_ * H_ * P_ * HD_];
__device__ float g_kh[B_ * H_ * P_ * HD_];
__device__ float g_vh[B_ * H_ * P_ * HD_];
__device__ float g_vsum[B_ * H_ * P_ * HD_];
__device__ float g_rep[H_ * NF * HD_];

// ---------------------------------------------------------------------------
// Kernel 1: RMSNorm (over D=768) + head split for q, k, v.
// One block per (b, p) row. 256 threads, 3 elements/thread/tensor.
// ---------------------------------------------------------------------------
__global__ __launch_bounds__(256) void k_rms(
    const float* __restrict__ q, const float* __restrict__ k,
    const float* __restrict__ v, const float* __restrict__ wq,
    const float* __restrict__ wk, const float* __restrict__ wv)
{
    int bp = blockIdx.x;
    int b = bp / P_;
    int p = bp % P_;
    int tid = threadIdx.x;
    int lane = tid & 31, warp = tid >> 5;
    size_t off = (size_t)bp * D_;

    float xq[3], xk[3], xv[3];
    float sq = 0.f, sk = 0.f, sv = 0.f;
#pragma unroll
    for (int i = 0; i < 3; i++) {
        int j = tid + i * 256;
        xq[i] = q[off + j]; sq += xq[i] * xq[i];
        xk[i] = k[off + j]; sk += xk[i] * xk[i];
        xv[i] = v[off + j]; sv += xv[i] * xv[i];
    }
#pragma unroll
    for (int o = 16; o; o >>= 1) {
        sq += __shfl_xor_sync(0xffffffffu, sq, o);
        sk += __shfl_xor_sync(0xffffffffu, sk, o);
        sv += __shfl_xor_sync(0xffffffffu, sv, o);
    }
    __shared__ float s_q[8], s_k[8], s_v[8];
    if (lane == 0) { s_q[warp] = sq; s_k[warp] = sk; s_v[warp] = sv; }
    __syncthreads();
    float tq = 0.f, tk = 0.f, tv = 0.f;
#pragma unroll
    for (int w = 0; w < 8; w++) { tq += s_q[w]; tk += s_k[w]; tv += s_v[w]; }
    float rq = rsqrtf(tq * (1.0f / D_) + 1e-6f);
    float rk = rsqrtf(tk * (1.0f / D_) + 1e-6f);
    float rv = rsqrtf(tv * (1.0f / D_) + 1e-6f);

#pragma unroll
    for (int i = 0; i < 3; i++) {
        int j = tid + i * 256;
        int h = j >> 6, c = j & 63;
        int di = ((b * H_ + h) * P_ + p) * HD_ + c;
        g_qh[di] = xq[i] * rq * wq[j];
        g_kh[di] = xk[i] * rk * wk[j];
        g_vh[di] = xv[i] * rv * wv[j];
    }
}

// ---------------------------------------------------------------------------
// Kernel 2: gather representative tokens:
// g_rep[h][nn*49+j][c] = g_vh[nn][h][idx[j]][c]
// ---------------------------------------------------------------------------
__global__ __launch_bounds__(256) void k_rep(const int* __restrict__ idxs)
{
    int t = blockIdx.x * 256 + threadIdx.x;
    if (t >= H_ * NF * HD_) return;
    int c  = t & 63;
    int rj = (t >> 6) % NF;
    int h  = t / (NF * HD_);
    int nn = rj / PPR;
    int j  = rj % PPR;
    int sp = idxs[j];
    g_rep[t] = g_vh[((nn * H_ + h) * P_ + sp) * HD_ + c];
}

// ---------------------------------------------------------------------------
// Kernel 3: sim + top-8 threshold + sparse softmax + v_aligned.
// Block handles PT=4 query rows of one (b, h). Writes g_vsum = vh + v_aligned.
// ---------------------------------------------------------------------------
__global__ __launch_bounds__(256) void k_align()
{
    int bid = blockIdx.x;
    int t  = bid % NT;
    int h  = (bid / NT) % H_;
    int b  = bid / (NT * H_);
    int p0 = t * PT;
    int nr = min(PT, P_ - p0);
    int tid = threadIdx.x;
    int lane = tid & 31, warp = tid >> 5;

    __shared__ float vrow[PT][HD_];
    __shared__ float sim[PT][NF];
    __shared__ float simw[NF];
    __shared__ int   kept[NF];
    __shared__ float rred[8];
    __shared__ int   ired[8];
    __shared__ int   wcnt[8], wbase[8];
    __shared__ float s_max, s_thr;
    __shared__ int   s_nk;

    // load the PT value rows
    for (int i = tid; i < nr * HD_; i += 256) {
        int r = i >> 6, c = i & 63;
        vrow[r][c] = g_vh[((b * H_ + h) * P_ + p0 + r) * HD_ + c];
    }
    __syncthreads();

    const float* rep = g_rep + (size_t)h * NF * HD_;
    int mlo = b * PPR;
    bool hasmask = (b < NREF);

    // sim[r][j] = vrow[r] . rep[j]  (64-d dot), with self mask
    for (int j = tid; j < NF; j += 256) {
        const float4* r4 = (const float4*)(rep + (size_t)j * HD_);
        float a[PT];
#pragma unroll
        for (int r = 0; r < PT; r++) a[r] = 0.f;
#pragma unroll
        for (int c4 = 0; c4 < 16; c4++) {
            float4 rr = __ldg(r4 + c4);
#pragma unroll
            for (int r = 0; r < PT; r++) {
                a[r] += rr.x * vrow[r][4 * c4 + 0];
                a[r] += rr.y * vrow[r][4 * c4 + 1];
                a[r] += rr.z * vrow[r][4 * c4 + 2];
                a[r] += rr.w * vrow[r][4 * c4 + 3];
            }
        }
        bool selfm = hasmask && (j >= mlo) && (j < mlo + PPR);
#pragma unroll
        for (int r = 0; r < PT; r++) sim[r][j] = selfm ? NEGF : a[r];
    }
    __syncthreads();

    for (int r = 0; r < nr; r++) {
        // working copy for extraction
        for (int j = tid; j < NF; j += 256) simw[j] = sim[r][j];
        __syncthreads();

        // 8 deterministic arg-max extractions -> s_max (1st), s_thr (8th)
        for (int it = 0; it < TK; it++) {
            float bv = -CUDART_INF_F; int bi = 0;
            for (int j = tid; j < NF; j += 256) {
                float x = simw[j];
                if (x > bv) { bv = x; bi = j; }
            }
#pragma unroll
            for (int o = 16; o; o >>= 1) {
                float ov = __shfl_down_sync(0xffffffffu, bv, o);
                int   oi = __shfl_down_sync(0xffffffffu, bi, o);
                if (ov > bv) { bv = ov; bi = oi; }
            }
            if (lane == 0) { rred[warp] = bv; ired[warp] = bi; }
            __syncthreads();
            if (warp == 0) {
                bv = (lane < 8) ? rred[lane] : -CUDART_INF_F;
                bi = (lane < 8) ? ired[lane] : 0;
#pragma unroll
                for (int o = 4; o; o >>= 1) {
                    float ov = __shfl_down_sync(0xffffffffu, bv, o);
                    int   oi = __shfl_down_sync(0xffffffffu, bi, o);
                    if (ov > bv) { bv = ov; bi = oi; }
                }
                if (lane == 0) {
                    if (it == 0)      s_max = bv;
                    if (it == TK - 1) s_thr = bv;
                    simw[bi] = -CUDART_INF_F;
                }
            }
            __syncthreads();
        }
        float thr = s_thr, mx = s_max;

        // softmax denominator over kept entries (>= thr); others are exactly 0
        float ps = 0.f;
        for (int j = tid; j < NF; j += 256) {
            float x = sim[r][j];
            if (x >= thr) ps += expf(x - mx);
        }
#pragma unroll
        for (int o = 16; o; o >>= 1) ps += __shfl_xor_sync(0xffffffffu, ps, o);
        if (lane == 0) rred[warp] = ps;

        // deterministic compaction of kept indices (per-warp contiguous ranges)
        int jlo = warp * 98, jhi = jlo + 98;   // 8*98 = 784
        int cnt = 0;
        for (int j0 = jlo; j0 < jhi; j0 += 32) {
            int j = j0 + lane;
            bool keep = (j < jhi) && (sim[r][j] >= thr);
            unsigned m = __ballot_sync(0xffffffffu, keep);
            cnt += __popc(m);
        }
        if (lane == 0) wcnt[warp] = cnt;
        __syncthreads();
        if (tid == 0) {
            int s = 0;
#pragma unroll
            for (int w = 0; w < 8; w++) { wbase[w] = s; s += wcnt[w]; }
            s_nk = s;
        }
        __syncthreads();
        float tot = 0.f;
#pragma unroll
        for (int w = 0; w < 8; w++) tot += rred[w];
        float inv = 1.0f / tot;

        int pos = wbase[warp];
        for (int j0 = jlo; j0 < jhi; j0 += 32) {
            int j = j0 + lane;
            bool keep = (j < jhi) && (sim[r][j] >= thr);
            unsigned m = __ballot_sync(0xffffffffu, keep);
            if (keep) kept[pos + __popc(m & ((1u << lane) - 1u))] = j;
            pos += __popc(m);
        }
        __syncthreads();

        // v_aligned accumulation over ~8 kept refs; write vsum = vh + aligned
        if (tid < HD_) {
            float acc = vrow[r][tid];
            int nk = s_nk;
            for (int kk = 0; kk < nk; kk++) {
                int j = kept[kk];
                float w = expf(sim[r][j] - mx) * inv;
                acc += w * __ldg(rep + (size_t)j * HD_ + tid);
            }
            g_vsum[((b * H_ + h) * P_ + p0 + r) * HD_ + tid] = acc;
        }
        __syncthreads();
    }
}

// ---------------------------------------------------------------------------
// Kernel 4: standard attention: softmax(q k^T * 0.125) @ vsum -> out (B,P,D)
// Block handles PT=4 query rows of one (b, h).
// ---------------------------------------------------------------------------
__global__ __launch_bounds__(256) void k_attn(float* __restrict__ out)
{
    int bid = blockIdx.x;
    int t  = bid % NT;
    int h  = (bid / NT) % H_;
    int b  = bid / (NT * H_);
    int p0 = t * PT;
    int nr = min(PT, P_ - p0);
    int tid = threadIdx.x;
    int lane = tid & 31, warp = tid >> 5;

    __shared__ float qrow[PT][HD_];
    __shared__ float prob[PT][P_];
    __shared__ float rred[8];
    __shared__ float s_inv[PT];
    __shared__ float part[4][PT][HD_];

    for (int i = tid; i < nr * HD_; i += 256) {
        int r = i >> 6, c = i & 63;
        qrow[r][c] = g_qh[((b * H_ + h) * P_ + p0 + r) * HD_ + c];
    }
    __syncthreads();

    const float* kb = g_kh + (size_t)(b * H_ + h) * P_ * HD_;
    for (int j = tid; j < P_; j += 256) {
        const float4* k4 = (const float4*)(kb + (size_t)j * HD_);
        float a[PT];
#pragma unroll
        for (int r = 0; r < PT; r++) a[r] = 0.f;
#pragma unroll
        for (int c4 = 0; c4 < 16; c4++) {
            float4 kk = __ldg(k4 + c4);
#pragma unroll
            for (int r = 0; r < PT; r++) {
                a[r] += kk.x * qrow[r][4 * c4 + 0];
                a[r] += kk.y * qrow[r][4 * c4 + 1];
                a[r] += kk.z * qrow[r][4 * c4 + 2];
                a[r] += kk.w * qrow[r][4 * c4 + 3];
            }
        }
#pragma unroll
        for (int r = 0; r < PT; r++) prob[r][j] = a[r] * 0.125f;
    }
    __syncthreads();

    for (int r = 0; r < nr; r++) {
        // row max
        float bv = -CUDART_INF_F;
        for (int j = tid; j < P_; j += 256) bv = fmaxf(bv, prob[r][j]);
#pragma unroll
        for (int o = 16; o; o >>= 1)
            bv = fmaxf(bv, __shfl_xor_sync(0xffffffffu, bv, o));
        if (lane == 0) rred[warp] = bv;
        __syncthreads();
        float mx = -CUDART_INF_F;
#pragma unroll
        for (int w = 0; w < 8; w++) mx = fmaxf(mx, rred[w]);
        __syncthreads();
        // exp + sum
        float ps = 0.f;
        for (int j = tid; j < P_; j += 256) {
            float e = expf(prob[r][j] - mx);
            prob[r][j] = e;
            ps += e;
        }
#pragma unroll
        for (int o = 16; o; o >>= 1) ps += __shfl_xor_sync(0xffffffffu, ps, o);
        if (lane == 0) rred[warp] = ps;
        __syncthreads();
        float tot = 0.f;
#pragma unroll
        for (int w = 0; w < 8; w++) tot += rred[w];
        if (tid == 0) s_inv[r] = 1.0f / tot;
        __syncthreads();
    }

    // output accumulation: groups of 64 threads split the j range
    int c = tid & 63, g = tid >> 6;
    float acc[PT];
#pragma unroll
    for (int r = 0; r < PT; r++) acc[r] = 0.f;
    const float* vb = g_vsum + (size_t)(b * H_ + h) * P_ * HD_;
    for (int j = g; j < P_; j += 4) {
        float v = __ldg(vb + (size_t)j * HD_ + c);
#pragma unroll
        for (int r = 0; r < PT; r++) acc[r] += prob[r][j] * v;
    }
#pragma unroll
    for (int r = 0; r < PT; r++) part[g][r][c] = acc[r];
    __syncthreads();

    int rr = tid >> 6, cc = tid & 63;
    if (rr < nr) {
        float s = part[0][rr][cc] + part[1][rr][cc] + part[2][rr][cc] + part[3][rr][cc];
        out[((size_t)b * P_ + p0 + rr) * D_ + h * HD_ + cc] = s * s_inv[rr];
    }
}

// ---------------------------------------------------------------------------
extern "C" void kernel_launch(void* const* d_in, const int* in_sizes, int n_in,
                              void* d_out, int out_size)
{
    const float* q   = (const float*)d_in[0];
    const float* k   = (const float*)d_in[1];
    const float* v   = (const float*)d_in[2];
    const float* wq  = (const float*)d_in[3];
    const float* wk  = (const float*)d_in[4];
    const float* wv  = (const float*)d_in[5];
    const int* idxs  = (const int*)d_in[6];
    float* out = (float*)d_out;

    k_rms<<<B_ * P_, 256>>>(q, k, v, wq, wk, wv);
    k_rep<<<(H_ * NF * HD_ + 255) / 256, 256>>>(idxs);
    k_align<<<B_ * H_ * NT, 256>>>();
    k_attn<<<B_ * H_ * NT, 256>>>(out);
}

// round 4
// speedup vs baseline: 1.0001x; 1.0001x over previous
#include <cuda_runtime.h>
#include <math_constants.h>

namespace {
constexpr int B_   = 32;
constexpr int P_   = 197;
constexpr int D_   = 768;
constexpr int H_   = 12;
constexpr int HD_  = 64;
constexpr int PPR  = 49;    // rep tokens per reference sample
constexpr int NREF = 16;    // int(B * 0.5)
constexpr int NF   = 784;   // NREF * PPR
constexpr int TK   = 8;     // top-k
constexpr int PT   = 4;     // query rows per block
constexpr int NT   = (P_ + PT - 1) / PT;  // 50
constexpr float NEGF = -1e30f;
}

// scratch (device globals; no allocation allowed)
__device__ float g_qh[B_ * H_ * P_ * HD_];
__device__ float g_kh[B_ * H_ * P_ * HD_];
__device__ float g_vh[B_ * H_ * P_ * HD_];
__device__ float g_vsum[B_ * H_ * P_ * HD_];
__device__ float g_rep[H_ * NF * HD_];

// ---------------------------------------------------------------------------
// Kernel 1: RMSNorm (over D=768) + head split for q, k, v.
// One block per (b, p) row. 256 threads, 3 elements/thread/tensor.
// ---------------------------------------------------------------------------
__global__ __launch_bounds__(256) void k_rms(
    const float* __restrict__ q, const float* __restrict__ k,
    const float* __restrict__ v, const float* __restrict__ wq,
    const float* __restrict__ wk, const float* __restrict__ wv)
{
    int bp = blockIdx.x;
    int b = bp / P_;
    int p = bp % P_;
    int tid = threadIdx.x;
    int lane = tid & 31, warp = tid >> 5;
    size_t off = (size_t)bp * D_;

    float xq[3], xk[3], xv[3];
    float sq = 0.f, sk = 0.f, sv = 0.f;
#pragma unroll
    for (int i = 0; i < 3; i++) {
        int j = tid + i * 256;
        xq[i] = q[off + j]; sq += xq[i] * xq[i];
        xk[i] = k[off + j]; sk += xk[i] * xk[i];
        xv[i] = v[off + j]; sv += xv[i] * xv[i];
    }
#pragma unroll
    for (int o = 16; o; o >>= 1) {
        sq += __shfl_xor_sync(0xffffffffu, sq, o);
        sk += __shfl_xor_sync(0xffffffffu, sk, o);
        sv += __shfl_xor_sync(0xffffffffu, sv, o);
    }
    __shared__ float s_q[8], s_k[8], s_v[8];
    if (lane == 0) { s_q[warp] = sq; s_k[warp] = sk; s_v[warp] = sv; }
    __syncthreads();
    float tq = 0.f, tk = 0.f, tv = 0.f;
#pragma unroll
    for (int w = 0; w < 8; w++) { tq += s_q[w]; tk += s_k[w]; tv += s_v[w]; }
    float rq = rsqrtf(tq * (1.0f / D_) + 1e-6f);
    float rk = rsqrtf(tk * (1.0f / D_) + 1e-6f);
    float rv = rsqrtf(tv * (1.0f / D_) + 1e-6f);

#pragma unroll
    for (int i = 0; i < 3; i++) {
        int j = tid + i * 256;
        int h = j >> 6, c = j & 63;
        int di = ((b * H_ + h) * P_ + p) * HD_ + c;
        g_qh[di] = xq[i] * rq * wq[j];
        g_kh[di] = xk[i] * rk * wk[j];
        g_vh[di] = xv[i] * rv * wv[j];
    }
}

// ---------------------------------------------------------------------------
// Kernel 2: gather representative tokens:
// g_rep[h][nn*49+j][c] = g_vh[nn][h][idx[j]][c]
// ---------------------------------------------------------------------------
__global__ __launch_bounds__(256) void k_rep(const int* __restrict__ idxs)
{
    int t = blockIdx.x * 256 + threadIdx.x;
    if (t >= H_ * NF * HD_) return;
    int c  = t & 63;
    int rj = (t >> 6) % NF;
    int h  = t / (NF * HD_);
    int nn = rj / PPR;
    int j  = rj % PPR;
    int sp = idxs[j];
    g_rep[t] = g_vh[((nn * H_ + h) * P_ + sp) * HD_ + c];
}

// ---------------------------------------------------------------------------
// Kernel 3: sim + top-8 threshold + sparse softmax + v_aligned.
// Block handles PT=4 query rows of one (b, h). Writes g_vsum = vh + v_aligned.
// ---------------------------------------------------------------------------
__global__ __launch_bounds__(256) void k_align()
{
    int bid = blockIdx.x;
    int t  = bid % NT;
    int h  = (bid / NT) % H_;
    int b  = bid / (NT * H_);
    int p0 = t * PT;
    int nr = min(PT, P_ - p0);
    int tid = threadIdx.x;
    int lane = tid & 31, warp = tid >> 5;

    __shared__ float vrow[PT][HD_];
    __shared__ float sim[PT][NF];
    __shared__ float simw[NF];
    __shared__ int   kept[NF];
    __shared__ float rred[8];
    __shared__ int   ired[8];
    __shared__ int   wcnt[8], wbase[8];
    __shared__ float s_max, s_thr;
    __shared__ int   s_nk;

    // load the PT value rows
    for (int i = tid; i < nr * HD_; i += 256) {
        int r = i >> 6, c = i & 63;
        vrow[r][c] = g_vh[((b * H_ + h) * P_ + p0 + r) * HD_ + c];
    }
    __syncthreads();

    const float* rep = g_rep + (size_t)h * NF * HD_;
    int mlo = b * PPR;
    bool hasmask = (b < NREF);

    // sim[r][j] = vrow[r] . rep[j]  (64-d dot), with self mask
    for (int j = tid; j < NF; j += 256) {
        const float4* r4 = (const float4*)(rep + (size_t)j * HD_);
        float a[PT];
#pragma unroll
        for (int r = 0; r < PT; r++) a[r] = 0.f;
#pragma unroll
        for (int c4 = 0; c4 < 16; c4++) {
            float4 rr = __ldg(r4 + c4);
#pragma unroll
            for (int r = 0; r < PT; r++) {
                a[r] += rr.x * vrow[r][4 * c4 + 0];
                a[r] += rr.y * vrow[r][4 * c4 + 1];
                a[r] += rr.z * vrow[r][4 * c4 + 2];
                a[r] += rr.w * vrow[r][4 * c4 + 3];
            }
        }
        bool selfm = hasmask && (j >= mlo) && (j < mlo + PPR);
#pragma unroll
        for (int r = 0; r < PT; r++) sim[r][j] = selfm ? NEGF : a[r];
    }
    __syncthreads();

    for (int r = 0; r < nr; r++) {
        // working copy for extraction
        for (int j = tid; j < NF; j += 256) simw[j] = sim[r][j];
        __syncthreads();

        // 8 deterministic arg-max extractions -> s_max (1st), s_thr (8th)
        for (int it = 0; it < TK; it++) {
            float bv = -CUDART_INF_F; int bi = 0;
            for (int j = tid; j < NF; j += 256) {
                float x = simw[j];
                if (x > bv) { bv = x; bi = j; }
            }
#pragma unroll
            for (int o = 16; o; o >>= 1) {
                float ov = __shfl_down_sync(0xffffffffu, bv, o);
                int   oi = __shfl_down_sync(0xffffffffu, bi, o);
                if (ov > bv) { bv = ov; bi = oi; }
            }
            if (lane == 0) { rred[warp] = bv; ired[warp] = bi; }
            __syncthreads();
            if (warp == 0) {
                bv = (lane < 8) ? rred[lane] : -CUDART_INF_F;
                bi = (lane < 8) ? ired[lane] : 0;
#pragma unroll
                for (int o = 4; o; o >>= 1) {
                    float ov = __shfl_down_sync(0xffffffffu, bv, o);
                    int   oi = __shfl_down_sync(0xffffffffu, bi, o);
                    if (ov > bv) { bv = ov; bi = oi; }
                }
                if (lane == 0) {
                    if (it == 0)      s_max = bv;
                    if (it == TK - 1) s_thr = bv;
                    simw[bi] = -CUDART_INF_F;
                }
            }
            __syncthreads();
        }
        float thr = s_thr, mx = s_max;

        // softmax denominator over kept entries (>= thr); others are exactly 0
        float ps = 0.f;
        for (int j = tid; j < NF; j += 256) {
            float x = sim[r][j];
            if (x >= thr) ps += expf(x - mx);
        }
#pragma unroll
        for (int o = 16; o; o >>= 1) ps += __shfl_xor_sync(0xffffffffu, ps, o);
        if (lane == 0) rred[warp] = ps;

        // deterministic compaction of kept indices (per-warp contiguous ranges)
        int jlo = warp * 98, jhi = jlo + 98;   // 8*98 = 784
        int cnt = 0;
        for (int j0 = jlo; j0 < jhi; j0 += 32) {
            int j = j0 + lane;
            bool keep = (j < jhi) && (sim[r][j] >= thr);
            unsigned m = __ballot_sync(0xffffffffu, keep);
            cnt += __popc(m);
        }
        if (lane == 0) wcnt[warp] = cnt;
        __syncthreads();
        if (tid == 0) {
            int s = 0;
#pragma unroll
            for (int w = 0; w < 8; w++) { wbase[w] = s; s += wcnt[w]; }
            s_nk = s;
        }
        __syncthreads();
        float tot = 0.f;
#pragma unroll
        for (int w = 0; w < 8; w++) tot += rred[w];
        float inv = 1.0f / tot;

        int pos = wbase[warp];
        for (int j0 = jlo; j0 < jhi; j0 += 32) {
            int j = j0 + lane;
            bool keep = (j < jhi) && (sim[r][j] >= thr);
            unsigned m = __ballot_sync(0xffffffffu, keep);
            if (keep) kept[pos + __popc(m & ((1u << lane) - 1u))] = j;
            pos += __popc(m);
        }
        __syncthreads();

        // v_aligned accumulation over ~8 kept refs; write vsum = vh + aligned
        if (tid < HD_) {
            float acc = vrow[r][tid];
            int nk = s_nk;
            for (int kk = 0; kk < nk; kk++) {
                int j = kept[kk];
                float w = expf(sim[r][j] - mx) * inv;
                acc += w * __ldg(rep + (size_t)j * HD_ + tid);
            }
            g_vsum[((b * H_ + h) * P_ + p0 + r) * HD_ + tid] = acc;
        }
        __syncthreads();
    }
}

// ---------------------------------------------------------------------------
// Kernel 4: standard attention: softmax(q k^T * 0.125) @ vsum -> out (B,P,D)
// Block handles PT=4 query rows of one (b, h).
// ---------------------------------------------------------------------------
__global__ __launch_bounds__(256) void k_attn(float* __restrict__ out)
{
    int bid = blockIdx.x;
    int t  = bid % NT;
    int h  = (bid / NT) % H_;
    int b  = bid / (NT * H_);
    int p0 = t * PT;
    int nr = min(PT, P_ - p0);
    int tid = threadIdx.x;
    int lane = tid & 31, warp = tid >> 5;

    __shared__ float qrow[PT][HD_];
    __shared__ float prob[PT][P_];
    __shared__ float rred[8];
    __shared__ float s_inv[PT];
    __shared__ float part[4][PT][HD_];

    for (int i = tid; i < nr * HD_; i += 256) {
        int r = i >> 6, c = i & 63;
        qrow[r][c] = g_qh[((b * H_ + h) * P_ + p0 + r) * HD_ + c];
    }
    __syncthreads();

    const float* kb = g_kh + (size_t)(b * H_ + h) * P_ * HD_;
    for (int j = tid; j < P_; j += 256) {
        const float4* k4 = (const float4*)(kb + (size_t)j * HD_);
        float a[PT];
#pragma unroll
        for (int r = 0; r < PT; r++) a[r] = 0.f;
#pragma unroll
        for (int c4 = 0; c4 < 16; c4++) {
            float4 kk = __ldg(k4 + c4);
#pragma unroll
            for (int r = 0; r < PT; r++) {
                a[r] += kk.x * qrow[r][4 * c4 + 0];
                a[r] += kk.y * qrow[r][4 * c4 + 1];
                a[r] += kk.z * qrow[r][4 * c4 + 2];
                a[r] += kk.w * qrow[r][4 * c4 + 3];
            }
        }
#pragma unroll
        for (int r = 0; r < PT; r++) prob[r][j] = a[r] * 0.125f;
    }
    __syncthreads();

    for (int r = 0; r < nr; r++) {
        // row max
        float bv = -CUDART_INF_F;
        for (int j = tid; j < P_; j += 256) bv = fmaxf(bv, prob[r][j]);
#pragma unroll
        for (int o = 16; o; o >>= 1)
            bv = fmaxf(bv, __shfl_xor_sync(0xffffffffu, bv, o));
        if (lane == 0) rred[warp] = bv;
        __syncthreads();
        float mx = -CUDART_INF_F;
#pragma unroll
        for (int w = 0; w < 8; w++) mx = fmaxf(mx, rred[w]);
        __syncthreads();
        // exp + sum
        float ps = 0.f;
        for (int j = tid; j < P_; j += 256) {
            float e = expf(prob[r][j] - mx);
            prob[r][j] = e;
            ps += e;
        }
#pragma unroll
        for (int o = 16; o; o >>= 1) ps += __shfl_xor_sync(0xffffffffu, ps, o);
        if (lane == 0) rred[warp] = ps;
        __syncthreads();
        float tot = 0.f;
#pragma unroll
        for (int w = 0; w < 8; w++) tot += rred[w];
        if (tid == 0) s_inv[r] = 1.0f / tot;
        __syncthreads();
    }

    // output accumulation: groups of 64 threads split the j range
    int c = tid & 63, g = tid >> 6;
    float acc[PT];
#pragma unroll
    for (int r = 0; r < PT; r++) acc[r] = 0.f;
    const float* vb = g_vsum + (size_t)(b * H_ + h) * P_ * HD_;
    for (int j = g; j < P_; j += 4) {
        float v = __ldg(vb + (size_t)j * HD_ + c);
#pragma unroll
        for (int r = 0; r < PT; r++) acc[r] += prob[r][j] * v;
    }
#pragma unroll
    for (int r = 0; r < PT; r++) part[g][r][c] = acc[r];
    __syncthreads();

    int rr = tid >> 6, cc = tid & 63;
    if (rr < nr) {
        float s = part[0][rr][cc] + part[1][rr][cc] + part[2][rr][cc] + part[3][rr][cc];
        out[((size_t)b * P_ + p0 + rr) * D_ + h * HD_ + cc] = s * s_inv[rr];
    }
}

// ---------------------------------------------------------------------------
extern "C" void kernel_launch(void* const* d_in, const int* in_sizes, int n_in,
                              void* d_out, int out_size)
{
    const float* q   = (const float*)d_in[0];
    const float* k   = (const float*)d_in[1];
    const float* v   = (const float*)d_in[2];
    const float* wq  = (const float*)d_in[3];
    const float* wk  = (const float*)d_in[4];
    const float* wv  = (const float*)d_in[5];
    const int* idxs  = (const int*)d_in[6];
    float* out = (float*)d_out;

    k_rms<<<B_ * P_, 256>>>(q, k, v, wq, wk, wv);
    k_rep<<<(H_ * NF * HD_ + 255) / 256, 256>>>(idxs);
    k_align<<<B_ * H_ * NT, 256>>>();
    k_attn<<<B_ * H_ * NT, 256>>>(out);
}

// round 5
// speedup vs baseline: 2.4553x; 2.4550x over previous
#include <cuda_runtime.h>
#include <math_constants.h>

typedef unsigned long long ull;

namespace {
constexpr int B_   = 32;
constexpr int P_   = 197;
constexpr int D_   = 768;
constexpr int H_   = 12;
constexpr int HD_  = 64;
constexpr int PPR  = 49;    // rep tokens per reference sample
constexpr int NREF = 16;    // int(B * 0.5)
constexpr int NF   = 784;   // NREF * PPR
constexpr int PT   = 8;     // rows per block (one warp per row in phases 2/3)
constexpr int NT   = (P_ + PT - 1) / PT;  // 25
constexpr float NEGF = -1e30f;
}

// scratch (device globals; no allocation allowed)
__device__ float g_qh  [B_ * H_ * P_ * HD_];
__device__ float g_kh  [B_ * H_ * P_ * HD_];
__device__ float g_vh  [B_ * H_ * P_ * HD_];
__device__ float g_vsum[B_ * H_ * P_ * HD_];
__device__ float g_rep [H_ * NF * HD_];

// ---- packed f32x2 helpers (sm_103a) --------------------------------------
__device__ __forceinline__ ull pack2(float x, float y) {
    ull r; asm("mov.b64 %0, {%1, %2};" : "=l"(r) : "f"(x), "f"(y)); return r;
}
__device__ __forceinline__ ull fma2(ull a, ull b, ull c) {
    ull d; asm("fma.rn.f32x2 %0, %1, %2, %3;" : "=l"(d) : "l"(a), "l"(b), "l"(c));
    return d;
}
__device__ __forceinline__ void unpack2(ull p, float& x, float& y) {
    asm("mov.b64 {%0, %1}, %2;" : "=f"(x), "=f"(y) : "l"(p));
}
__device__ __forceinline__ float f4c(const float4& v, int q) {
    return q == 0 ? v.x : q == 1 ? v.y : q == 2 ? v.z : v.w;
}

// ---------------------------------------------------------------------------
// Kernel 1: RMSNorm (over D=768) + head split for q, k, v.
// ---------------------------------------------------------------------------
__global__ __launch_bounds__(256) void k_rms(
    const float* __restrict__ q, const float* __restrict__ k,
    const float* __restrict__ v, const float* __restrict__ wq,
    const float* __restrict__ wk, const float* __restrict__ wv)
{
    int bp = blockIdx.x;
    int b = bp / P_;
    int p = bp % P_;
    int tid = threadIdx.x;
    int lane = tid & 31, warp = tid >> 5;
    size_t off = (size_t)bp * D_;

    float xq[3], xk[3], xv[3];
    float sq = 0.f, sk = 0.f, sv = 0.f;
#pragma unroll
    for (int i = 0; i < 3; i++) {
        int j = tid + i * 256;
        xq[i] = q[off + j]; sq += xq[i] * xq[i];
        xk[i] = k[off + j]; sk += xk[i] * xk[i];
        xv[i] = v[off + j]; sv += xv[i] * xv[i];
    }
#pragma unroll
    for (int o = 16; o; o >>= 1) {
        sq += __shfl_xor_sync(0xffffffffu, sq, o);
        sk += __shfl_xor_sync(0xffffffffu, sk, o);
        sv += __shfl_xor_sync(0xffffffffu, sv, o);
    }
    __shared__ float s_q[8], s_k[8], s_v[8];
    if (lane == 0) { s_q[warp] = sq; s_k[warp] = sk; s_v[warp] = sv; }
    __syncthreads();
    float tq = 0.f, tk = 0.f, tv = 0.f;
#pragma unroll
    for (int w = 0; w < 8; w++) { tq += s_q[w]; tk += s_k[w]; tv += s_v[w]; }
    float rq = rsqrtf(tq * (1.0f / D_) + 1e-6f);
    float rk = rsqrtf(tk * (1.0f / D_) + 1e-6f);
    float rv = rsqrtf(tv * (1.0f / D_) + 1e-6f);

#pragma unroll
    for (int i = 0; i < 3; i++) {
        int j = tid + i * 256;
        int h = j >> 6, c = j & 63;
        int di = ((b * H_ + h) * P_ + p) * HD_ + c;
        g_qh[di] = xq[i] * rq * wq[j];
        g_kh[di] = xk[i] * rk * wk[j];
        g_vh[di] = xv[i] * rv * wv[j];
    }
}

// ---------------------------------------------------------------------------
// Kernel 2: gather representative tokens.
// ---------------------------------------------------------------------------
__global__ __launch_bounds__(256) void k_rep(const int* __restrict__ idxs)
{
    int t = blockIdx.x * 256 + threadIdx.x;
    if (t >= H_ * NF * HD_) return;
    int c  = t & 63;
    int rj = (t >> 6) % NF;
    int h  = t / (NF * HD_);
    int nn = rj / PPR;
    int j  = rj % PPR;
    int sp = idxs[j];
    g_rep[t] = g_vh[((nn * H_ + h) * P_ + sp) * HD_ + c];
}

// ---------------------------------------------------------------------------
// Kernel 3: sim + warp-local top-8 threshold + sparse softmax + v_aligned.
// Block = 8 warps = PT=8 rows of one (b, h). Writes g_vsum = vh + v_aligned.
// ---------------------------------------------------------------------------
__global__ __launch_bounds__(256) void k_align()
{
    int bid = blockIdx.x;
    int t  = bid % NT;
    int h  = (bid / NT) % H_;
    int b  = bid / (NT * H_);
    int p0 = t * PT;
    int tid = threadIdx.x;
    int lane = tid & 31, warp = tid >> 5;

    __shared__ float2 vp[4][HD_];       // row pairs (2pr, 2pr+1)
    __shared__ float  sim[PT][NF];
    __shared__ int    kj[PT][64];
    __shared__ float  kw[PT][64];

    const float* vbase = g_vh + (size_t)(b * H_ + h) * P_ * HD_;

    // load row pairs
    for (int i = tid; i < 4 * HD_; i += 256) {
        int pr = i >> 6, c = i & 63;
        int r0 = p0 + 2 * pr;
        float a = (r0     < P_) ? vbase[(size_t)r0 * HD_ + c]       : 0.f;
        float d = (r0 + 1 < P_) ? vbase[(size_t)(r0 + 1) * HD_ + c] : 0.f;
        vp[pr][c] = make_float2(a, d);
    }
    __syncthreads();

    const float* rep = g_rep + (size_t)h * NF * HD_;
    int mlo = b * PPR;
    bool hasmask = (b < NREF);

    // Phase 1: sim[r][j] = vrow[r] . rep[j], 4 j's per thread (784 = 196*4)
    for (int jb = tid * 4; jb < NF; jb += 1024) {
        ull acc[4][4];   // [jj][pr]
#pragma unroll
        for (int jj = 0; jj < 4; jj++)
#pragma unroll
            for (int pr = 0; pr < 4; pr++) acc[jj][pr] = 0ull;

        const float4* r40 = (const float4*)(rep + (size_t)(jb + 0) * HD_);
        const float4* r41 = (const float4*)(rep + (size_t)(jb + 1) * HD_);
        const float4* r42 = (const float4*)(rep + (size_t)(jb + 2) * HD_);
        const float4* r43 = (const float4*)(rep + (size_t)(jb + 3) * HD_);

#pragma unroll 4
        for (int c4 = 0; c4 < 16; c4++) {
            float4 rr0 = __ldg(r40 + c4);
            float4 rr1 = __ldg(r41 + c4);
            float4 rr2 = __ldg(r42 + c4);
            float4 rr3 = __ldg(r43 + c4);
#pragma unroll
            for (int q = 0; q < 4; q++) {
                int c = 4 * c4 + q;
                ull v0 = *(const ull*)&vp[0][c];
                ull v1 = *(const ull*)&vp[1][c];
                ull v2 = *(const ull*)&vp[2][c];
                ull v3 = *(const ull*)&vp[3][c];
                ull a2;
                a2 = pack2(f4c(rr0, q), f4c(rr0, q));
                acc[0][0] = fma2(a2, v0, acc[0][0]);
                acc[0][1] = fma2(a2, v1, acc[0][1]);
                acc[0][2] = fma2(a2, v2, acc[0][2]);
                acc[0][3] = fma2(a2, v3, acc[0][3]);
                a2 = pack2(f4c(rr1, q), f4c(rr1, q));
                acc[1][0] = fma2(a2, v0, acc[1][0]);
                acc[1][1] = fma2(a2, v1, acc[1][1]);
                acc[1][2] = fma2(a2, v2, acc[1][2]);
                acc[1][3] = fma2(a2, v3, acc[1][3]);
                a2 = pack2(f4c(rr2, q), f4c(rr2, q));
                acc[2][0] = fma2(a2, v0, acc[2][0]);
                acc[2][1] = fma2(a2, v1, acc[2][1]);
                acc[2][2] = fma2(a2, v2, acc[2][2]);
                acc[2][3] = fma2(a2, v3, acc[2][3]);
                a2 = pack2(f4c(rr3, q), f4c(rr3, q));
                acc[3][0] = fma2(a2, v0, acc[3][0]);
                acc[3][1] = fma2(a2, v1, acc[3][1]);
                acc[3][2] = fma2(a2, v2, acc[3][2]);
                acc[3][3] = fma2(a2, v3, acc[3][3]);
            }
        }
#pragma unroll
        for (int jj = 0; jj < 4; jj++) {
            int j = jb + jj;
            bool selfm = hasmask && (j >= mlo) && (j < mlo + PPR);
#pragma unroll
            for (int pr = 0; pr < 4; pr++) {
                float x, y;
                unpack2(acc[jj][pr], x, y);
                sim[2 * pr + 0][j] = selfm ? NEGF : x;
                sim[2 * pr + 1][j] = selfm ? NEGF : y;
            }
        }
    }
    __syncthreads();

    // Phases 2-3: one warp per row, no block barriers.
    int r = warp;
    int row = p0 + r;
    if (row < P_) {
        // lane-local sorted top-8 (descending) over this lane's 25 entries
        float s0 = -CUDART_INF_F, s1 = s0, s2 = s0, s3 = s0,
              s4 = s0, s5 = s0, s6 = s0, s7 = s0;
#pragma unroll
        for (int tt = 0; tt < 25; tt++) {
            int j = tt * 32 + lane;
            float v = (j < NF) ? sim[r][j] : -CUDART_INF_F;
            float m;
            m = fmaxf(s0, v); v = fminf(s0, v); s0 = m;
            m = fmaxf(s1, v); v = fminf(s1, v); s1 = m;
            m = fmaxf(s2, v); v = fminf(s2, v); s2 = m;
            m = fmaxf(s3, v); v = fminf(s3, v); s3 = m;
            m = fmaxf(s4, v); v = fminf(s4, v); s4 = m;
            m = fmaxf(s5, v); v = fminf(s5, v); s5 = m;
            m = fmaxf(s6, v); v = fminf(s6, v); s6 = m;
            m = fmaxf(s7, v); v = fminf(s7, v); s7 = m;
        }
        // merge across lanes: 8 rounds of warp-argmax with multiplicity
        float mx = 0.f, thr = 0.f;
#pragma unroll
        for (int it = 0; it < 8; it++) {
            float m = s0;
#pragma unroll
            for (int o = 16; o; o >>= 1)
                m = fmaxf(m, __shfl_xor_sync(0xffffffffu, m, o));
            if (it == 0) mx  = m;
            if (it == 7) thr = m;
            unsigned msk = __ballot_sync(0xffffffffu, s0 == m);
            if (lane == (__ffs(msk) - 1)) {     // consume one instance
                s0 = s1; s1 = s2; s2 = s3; s3 = s4;
                s4 = s5; s5 = s6; s6 = s7; s7 = -CUDART_INF_F;
            }
        }

        // denominator over kept (>= thr)
        float ps = 0.f;
#pragma unroll
        for (int tt = 0; tt < 25; tt++) {
            int j = tt * 32 + lane;
            if (j < NF) {
                float v = sim[r][j];
                if (v >= thr) ps += expf(v - mx);
            }
        }
#pragma unroll
        for (int o = 16; o; o >>= 1)
            ps += __shfl_xor_sync(0xffffffffu, ps, o);
        float inv = 1.0f / ps;

        // compact kept (j, weight) deterministically
        int base = 0;
#pragma unroll
        for (int tt = 0; tt < 25; tt++) {
            int j = tt * 32 + lane;
            bool keep = (j < NF) && (sim[r][j] >= thr);
            unsigned m2 = __ballot_sync(0xffffffffu, keep);
            if (keep) {
                int pos = base + __popc(m2 & ((1u << lane) - 1u));
                if (pos < 64) {
                    kj[r][pos] = j;
                    kw[r][pos] = expf(sim[r][j] - mx) * inv;
                }
            }
            base += __popc(m2);
        }
        int nk = min(base, 64);
        __syncwarp();

        // gather: lane owns columns 2*lane, 2*lane+1
        float2 vv = *(const float2*)(vbase + (size_t)row * HD_ + 2 * lane);
        float a0 = vv.x, a1 = vv.y;
        for (int kk = 0; kk < nk; kk++) {
            int jx = kj[r][kk];
            float w = kw[r][kk];
            float2 rv = *(const float2*)(rep + (size_t)jx * HD_ + 2 * lane);
            a0 += w * rv.x;
            a1 += w * rv.y;
        }
        *(float2*)(g_vsum + ((size_t)(b * H_ + h) * P_ + row) * HD_ + 2 * lane)
            = make_float2(a0, a1);
    }
}

// ---------------------------------------------------------------------------
// Kernel 4: attention: softmax(q k^T * 0.125) @ vsum -> out (B,P,D).
// Block = PT=8 rows of one (b, h); warp-per-row softmax.
// ---------------------------------------------------------------------------
__global__ __launch_bounds__(256) void k_attn(float* __restrict__ out)
{
    int bid = blockIdx.x;
    int t  = bid % NT;
    int h  = (bid / NT) % H_;
    int b  = bid / (NT * H_);
    int p0 = t * PT;
    int tid = threadIdx.x;
    int lane = tid & 31, warp = tid >> 5;

    __shared__ float2 qp[4][HD_];       // q row pairs
    __shared__ float2 probp[4][P_];     // prob row pairs
    __shared__ float  s_inv[PT];
    __shared__ float  part[4][PT][HD_];

    const float* qbase = g_qh + (size_t)(b * H_ + h) * P_ * HD_;
    for (int i = tid; i < 4 * HD_; i += 256) {
        int pr = i >> 6, c = i & 63;
        int r0 = p0 + 2 * pr;
        float a = (r0     < P_) ? qbase[(size_t)r0 * HD_ + c]       : 0.f;
        float d = (r0 + 1 < P_) ? qbase[(size_t)(r0 + 1) * HD_ + c] : 0.f;
        qp[pr][c] = make_float2(a, d);
    }
    __syncthreads();

    // Phase A: logits, 2 j per thread
    const float* kb = g_kh + (size_t)(b * H_ + h) * P_ * HD_;
    for (int jb = tid * 2; jb < P_; jb += 512) {
        int j0 = jb;
        int j1 = jb + 1;
        bool hv1 = (j1 < P_);
        const float4* k40 = (const float4*)(kb + (size_t)j0 * HD_);
        const float4* k41 = (const float4*)(kb + (size_t)(hv1 ? j1 : j0) * HD_);
        ull a0[4], a1[4];
#pragma unroll
        for (int pr = 0; pr < 4; pr++) { a0[pr] = 0ull; a1[pr] = 0ull; }
#pragma unroll 4
        for (int c4 = 0; c4 < 16; c4++) {
            float4 kk0 = __ldg(k40 + c4);
            float4 kk1 = __ldg(k41 + c4);
#pragma unroll
            for (int q = 0; q < 4; q++) {
                int c = 4 * c4 + q;
                ull v0 = *(const ull*)&qp[0][c];
                ull v1 = *(const ull*)&qp[1][c];
                ull v2 = *(const ull*)&qp[2][c];
                ull v3 = *(const ull*)&qp[3][c];
                ull r02 = pack2(f4c(kk0, q), f4c(kk0, q));
                a0[0] = fma2(r02, v0, a0[0]);
                a0[1] = fma2(r02, v1, a0[1]);
                a0[2] = fma2(r02, v2, a0[2]);
                a0[3] = fma2(r02, v3, a0[3]);
                ull r12 = pack2(f4c(kk1, q), f4c(kk1, q));
                a1[0] = fma2(r12, v0, a1[0]);
                a1[1] = fma2(r12, v1, a1[1]);
                a1[2] = fma2(r12, v2, a1[2]);
                a1[3] = fma2(r12, v3, a1[3]);
            }
        }
#pragma unroll
        for (int pr = 0; pr < 4; pr++) {
            float x, y;
            unpack2(a0[pr], x, y);
            probp[pr][j0] = make_float2(x * 0.125f, y * 0.125f);
        }
        if (hv1) {
#pragma unroll
            for (int pr = 0; pr < 4; pr++) {
                float x, y;
                unpack2(a1[pr], x, y);
                probp[pr][j1] = make_float2(x * 0.125f, y * 0.125f);
            }
        }
    }
    __syncthreads();

    // Phase B: warp-per-row softmax (leaves un-normalized exp; 1/sum in s_inv)
    int r = warp;
    if (p0 + r < P_) {
        int pr = r >> 1, comp = r & 1;
        float vals[7];
        float vmax = -CUDART_INF_F;
#pragma unroll
        for (int tt = 0; tt < 7; tt++) {
            int j = tt * 32 + lane;
            float x = -CUDART_INF_F;
            if (j < P_) x = ((const float*)&probp[pr][j])[comp];
            vals[tt] = x;
            vmax = fmaxf(vmax, x);
        }
#pragma unroll
        for (int o = 16; o; o >>= 1)
            vmax = fmaxf(vmax, __shfl_xor_sync(0xffffffffu, vmax, o));
        float ps = 0.f;
#pragma unroll
        for (int tt = 0; tt < 7; tt++) {
            int j = tt * 32 + lane;
            if (j < P_) {
                float e = expf(vals[tt] - vmax);
                ps += e;
                ((float*)&probp[pr][j])[comp] = e;
            }
        }
#pragma unroll
        for (int o = 16; o; o >>= 1)
            ps += __shfl_xor_sync(0xffffffffu, ps, o);
        if (lane == 0) s_inv[r] = 1.0f / ps;
    }
    __syncthreads();

    // Phase C: AV. 4 j-groups x 64 columns; f32x2 row-pair accumulation.
    {
        int g = tid >> 6, c = tid & 63;
        ull acc2[4] = {0ull, 0ull, 0ull, 0ull};
        const float* vb = g_vsum + (size_t)(b * H_ + h) * P_ * HD_;
        for (int j = g; j < P_; j += 4) {
            float v = __ldg(vb + (size_t)j * HD_ + c);
            ull v2 = pack2(v, v);
#pragma unroll
            for (int pr = 0; pr < 4; pr++) {
                ull w = *(const ull*)&probp[pr][j];
                acc2[pr] = fma2(w, v2, acc2[pr]);
            }
        }
#pragma unroll
        for (int pr = 0; pr < 4; pr++) {
            float x, y;
            unpack2(acc2[pr], x, y);
            part[g][2 * pr + 0][c] = x;
            part[g][2 * pr + 1][c] = y;
        }
    }
    __syncthreads();

    // epilogue: normalize + write
    for (int rr = tid >> 6; rr < PT; rr += 4) {
        int cc = tid & 63;
        if (p0 + rr < P_) {
            float s = part[0][rr][cc] + part[1][rr][cc]
                    + part[2][rr][cc] + part[3][rr][cc];
            out[((size_t)b * P_ + p0 + rr) * D_ + h * HD_ + cc] = s * s_inv[rr];
        }
    }
}

// ---------------------------------------------------------------------------
extern "C" void kernel_launch(void* const* d_in, const int* in_sizes, int n_in,
                              void* d_out, int out_size)
{
    const float* q   = (const float*)d_in[0];
    const float* k   = (const float*)d_in[1];
    const float* v   = (const float*)d_in[2];
    const float* wq  = (const float*)d_in[3];
    const float* wk  = (const float*)d_in[4];
    const float* wv  = (const float*)d_in[5];
    const int* idxs  = (const int*)d_in[6];
    float* out = (float*)d_out;

    k_rms<<<B_ * P_, 256>>>(q, k, v, wq, wk, wv);
    k_rep<<<(H_ * NF * HD_ + 255) / 256, 256>>>(idxs);
    k_align<<<B_ * H_ * NT, 256>>>();
    k_attn<<<B_ * H_ * NT, 256>>>(out);
}

// round 6
// speedup vs baseline: 2.4838x; 1.0116x over previous
#include <cuda_runtime.h>
#include <math_constants.h>

typedef unsigned long long ull;

namespace {
constexpr int B_   = 32;
constexpr int P_   = 197;
constexpr int D_   = 768;
constexpr int H_   = 12;
constexpr int HD_  = 64;
constexpr int PPR  = 49;    // rep tokens per reference sample
constexpr int NREF = 16;    // int(B * 0.5)
constexpr int NF   = 784;   // NREF * PPR
constexpr int PT   = 8;     // rows per block (one warp per row in phases 2/3)
constexpr int NT   = (P_ + PT - 1) / PT;  // 25
constexpr float NEGF = -1e30f;
}

// scratch (device globals; no allocation allowed)
__device__ float g_qh  [B_ * H_ * P_ * HD_];
__device__ float g_kh  [B_ * H_ * P_ * HD_];
__device__ float g_vh  [B_ * H_ * P_ * HD_];
__device__ float g_vsum[B_ * H_ * P_ * HD_];
__device__ float g_rep [H_ * NF * HD_];

// ---- packed f32x2 helpers (sm_103a) --------------------------------------
__device__ __forceinline__ ull pack2(float x, float y) {
    ull r; asm("mov.b64 %0, {%1, %2};" : "=l"(r) : "f"(x), "f"(y)); return r;
}
__device__ __forceinline__ ull fma2(ull a, ull b, ull c) {
    ull d; asm("fma.rn.f32x2 %0, %1, %2, %3;" : "=l"(d) : "l"(a), "l"(b), "l"(c));
    return d;
}
__device__ __forceinline__ void unpack2(ull p, float& x, float& y) {
    asm("mov.b64 {%0, %1}, %2;" : "=f"(x), "=f"(y) : "l"(p));
}
__device__ __forceinline__ float f4c(const float4& v, int q) {
    return q == 0 ? v.x : q == 1 ? v.y : q == 2 ? v.z : v.w;
}
__device__ __forceinline__ ull lo2(const float4& v) {  // (x, y) as f32x2
    ull r; asm("mov.b64 %0, {%1, %2};" : "=l"(r) : "f"(v.x), "f"(v.y)); return r;
}
__device__ __forceinline__ ull hi2(const float4& v) {  // (z, w) as f32x2
    ull r; asm("mov.b64 %0, {%1, %2};" : "=l"(r) : "f"(v.z), "f"(v.w)); return r;
}

// ---------------------------------------------------------------------------
// Kernel 1: RMSNorm (over D=768) + head split for q, k, v.
// ---------------------------------------------------------------------------
__global__ __launch_bounds__(256) void k_rms(
    const float* __restrict__ q, const float* __restrict__ k,
    const float* __restrict__ v, const float* __restrict__ wq,
    const float* __restrict__ wk, const float* __restrict__ wv)
{
    int bp = blockIdx.x;
    int b = bp / P_;
    int p = bp % P_;
    int tid = threadIdx.x;
    int lane = tid & 31, warp = tid >> 5;
    size_t off = (size_t)bp * D_;

    float xq[3], xk[3], xv[3];
    float sq = 0.f, sk = 0.f, sv = 0.f;
#pragma unroll
    for (int i = 0; i < 3; i++) {
        int j = tid + i * 256;
        xq[i] = q[off + j]; sq += xq[i] * xq[i];
        xk[i] = k[off + j]; sk += xk[i] * xk[i];
        xv[i] = v[off + j]; sv += xv[i] * xv[i];
    }
#pragma unroll
    for (int o = 16; o; o >>= 1) {
        sq += __shfl_xor_sync(0xffffffffu, sq, o);
        sk += __shfl_xor_sync(0xffffffffu, sk, o);
        sv += __shfl_xor_sync(0xffffffffu, sv, o);
    }
    __shared__ float s_q[8], s_k[8], s_v[8];
    if (lane == 0) { s_q[warp] = sq; s_k[warp] = sk; s_v[warp] = sv; }
    __syncthreads();
    float tq = 0.f, tk = 0.f, tv = 0.f;
#pragma unroll
    for (int w = 0; w < 8; w++) { tq += s_q[w]; tk += s_k[w]; tv += s_v[w]; }
    float rq = rsqrtf(tq * (1.0f / D_) + 1e-6f);
    float rk = rsqrtf(tk * (1.0f / D_) + 1e-6f);
    float rv = rsqrtf(tv * (1.0f / D_) + 1e-6f);

#pragma unroll
    for (int i = 0; i < 3; i++) {
        int j = tid + i * 256;
        int h = j >> 6, c = j & 63;
        int di = ((b * H_ + h) * P_ + p) * HD_ + c;
        g_qh[di] = xq[i] * rq * wq[j];
        g_kh[di] = xk[i] * rk * wk[j];
        g_vh[di] = xv[i] * rv * wv[j];
    }
}

// ---------------------------------------------------------------------------
// Kernel 2: gather representative tokens.
// ---------------------------------------------------------------------------
__global__ __launch_bounds__(256) void k_rep(const int* __restrict__ idxs)
{
    int t = blockIdx.x * 256 + threadIdx.x;
    if (t >= H_ * NF * HD_) return;
    int c  = t & 63;
    int rj = (t >> 6) % NF;
    int h  = t / (NF * HD_);
    int nn = rj / PPR;
    int j  = rj % PPR;
    int sp = idxs[j];
    g_rep[t] = g_vh[((nn * H_ + h) * P_ + sp) * HD_ + c];
}

// ---------------------------------------------------------------------------
// Kernel 3: sim + warp-local top-8 threshold + sparse softmax + v_aligned.
// Block = 8 warps = PT=8 rows of one (b, h). Writes g_vsum = vh + v_aligned.
// vp4[pr][c2] = (row2pr[2c2], row2pr+1[2c2], row2pr[2c2+1], row2pr+1[2c2+1])
// ---------------------------------------------------------------------------
__global__ __launch_bounds__(256) void k_align()
{
    int bid = blockIdx.x;
    int t  = bid % NT;
    int h  = (bid / NT) % H_;
    int b  = bid / (NT * H_);
    int p0 = t * PT;
    int tid = threadIdx.x;
    int lane = tid & 31, warp = tid >> 5;

    __shared__ float4 vp4[4][32];       // row-pair operand tile (LDS.128)
    __shared__ float  sim[PT][NF];
    __shared__ int    kj[PT][64];
    __shared__ float  kw[PT][64];

    const float* vbase = g_vh + (size_t)(b * H_ + h) * P_ * HD_;

    // load row pairs, packed two columns per float4
    for (int i = tid; i < 4 * 32; i += 256) {
        int pr = i >> 5, c2 = i & 31;
        int c = 2 * c2;
        int r0 = p0 + 2 * pr;
        float a0 = (r0     < P_) ? vbase[(size_t)r0 * HD_ + c]           : 0.f;
        float b0 = (r0 + 1 < P_) ? vbase[(size_t)(r0 + 1) * HD_ + c]     : 0.f;
        float a1 = (r0     < P_) ? vbase[(size_t)r0 * HD_ + c + 1]       : 0.f;
        float b1 = (r0 + 1 < P_) ? vbase[(size_t)(r0 + 1) * HD_ + c + 1] : 0.f;
        vp4[pr][c2] = make_float4(a0, b0, a1, b1);
    }
    __syncthreads();

    const float* rep = g_rep + (size_t)h * NF * HD_;
    int mlo = b * PPR;
    bool hasmask = (b < NREF);

    // Phase 1: sim[r][j] = vrow[r] . rep[j], 4 j's per thread (784 = 196*4)
    for (int jb = tid * 4; jb < NF; jb += 1024) {
        ull acc[4][4];   // [jj][pr]
#pragma unroll
        for (int jj = 0; jj < 4; jj++)
#pragma unroll
            for (int pr = 0; pr < 4; pr++) acc[jj][pr] = 0ull;

        const float4* r40 = (const float4*)(rep + (size_t)(jb + 0) * HD_);
        const float4* r41 = (const float4*)(rep + (size_t)(jb + 1) * HD_);
        const float4* r42 = (const float4*)(rep + (size_t)(jb + 2) * HD_);
        const float4* r43 = (const float4*)(rep + (size_t)(jb + 3) * HD_);

#pragma unroll 2
        for (int c4 = 0; c4 < 16; c4++) {
            float4 rr0 = __ldg(r40 + c4);
            float4 rr1 = __ldg(r41 + c4);
            float4 rr2 = __ldg(r42 + c4);
            float4 rr3 = __ldg(r43 + c4);
#pragma unroll
            for (int qp = 0; qp < 2; qp++) {
                int c2 = 2 * c4 + qp;
                float4 vv0 = vp4[0][c2];
                float4 vv1 = vp4[1][c2];
                float4 vv2 = vp4[2][c2];
                float4 vv3 = vp4[3][c2];
                ull v0a = lo2(vv0), v0b = hi2(vv0);
                ull v1a = lo2(vv1), v1b = hi2(vv1);
                ull v2a = lo2(vv2), v2b = hi2(vv2);
                ull v3a = lo2(vv3), v3b = hi2(vv3);
                float ra0 = f4c(rr0, 2 * qp), rb0 = f4c(rr0, 2 * qp + 1);
                float ra1 = f4c(rr1, 2 * qp), rb1 = f4c(rr1, 2 * qp + 1);
                float ra2 = f4c(rr2, 2 * qp), rb2 = f4c(rr2, 2 * qp + 1);
                float ra3 = f4c(rr3, 2 * qp), rb3 = f4c(rr3, 2 * qp + 1);
                ull pa, pb;
                pa = pack2(ra0, ra0); pb = pack2(rb0, rb0);
                acc[0][0] = fma2(pa, v0a, acc[0][0]); acc[0][0] = fma2(pb, v0b, acc[0][0]);
                acc[0][1] = fma2(pa, v1a, acc[0][1]); acc[0][1] = fma2(pb, v1b, acc[0][1]);
                acc[0][2] = fma2(pa, v2a, acc[0][2]); acc[0][2] = fma2(pb, v2b, acc[0][2]);
                acc[0][3] = fma2(pa, v3a, acc[0][3]); acc[0][3] = fma2(pb, v3b, acc[0][3]);
                pa = pack2(ra1, ra1); pb = pack2(rb1, rb1);
                acc[1][0] = fma2(pa, v0a, acc[1][0]); acc[1][0] = fma2(pb, v0b, acc[1][0]);
                acc[1][1] = fma2(pa, v1a, acc[1][1]); acc[1][1] = fma2(pb, v1b, acc[1][1]);
                acc[1][2] = fma2(pa, v2a, acc[1][2]); acc[1][2] = fma2(pb, v2b, acc[1][2]);
                acc[1][3] = fma2(pa, v3a, acc[1][3]); acc[1][3] = fma2(pb, v3b, acc[1][3]);
                pa = pack2(ra2, ra2); pb = pack2(rb2, rb2);
                acc[2][0] = fma2(pa, v0a, acc[2][0]); acc[2][0] = fma2(pb, v0b, acc[2][0]);
                acc[2][1] = fma2(pa, v1a, acc[2][1]); acc[2][1] = fma2(pb, v1b, acc[2][1]);
                acc[2][2] = fma2(pa, v2a, acc[2][2]); acc[2][2] = fma2(pb, v2b, acc[2][2]);
                acc[2][3] = fma2(pa, v3a, acc[2][3]); acc[2][3] = fma2(pb, v3b, acc[2][3]);
                pa = pack2(ra3, ra3); pb = pack2(rb3, rb3);
                acc[3][0] = fma2(pa, v0a, acc[3][0]); acc[3][0] = fma2(pb, v0b, acc[3][0]);
                acc[3][1] = fma2(pa, v1a, acc[3][1]); acc[3][1] = fma2(pb, v1b, acc[3][1]);
                acc[3][2] = fma2(pa, v2a, acc[3][2]); acc[3][2] = fma2(pb, v2b, acc[3][2]);
                acc[3][3] = fma2(pa, v3a, acc[3][3]); acc[3][3] = fma2(pb, v3b, acc[3][3]);
            }
        }
#pragma unroll
        for (int jj = 0; jj < 4; jj++) {
            int j = jb + jj;
            bool selfm = hasmask && (j >= mlo) && (j < mlo + PPR);
#pragma unroll
            for (int pr = 0; pr < 4; pr++) {
                float x, y;
                unpack2(acc[jj][pr], x, y);
                sim[2 * pr + 0][j] = selfm ? NEGF : x;
                sim[2 * pr + 1][j] = selfm ? NEGF : y;
            }
        }
    }
    __syncthreads();

    // Phases 2-3: one warp per row, no block barriers.
    int r = warp;
    int row = p0 + r;
    if (row < P_) {
        // lane-local sorted top-8 (descending) over this lane's 25 entries
        float s0 = -CUDART_INF_F, s1 = s0, s2 = s0, s3 = s0,
              s4 = s0, s5 = s0, s6 = s0, s7 = s0;
#pragma unroll
        for (int tt = 0; tt < 25; tt++) {
            int j = tt * 32 + lane;
            float v = (j < NF) ? sim[r][j] : -CUDART_INF_F;
            float m;
            m = fmaxf(s0, v); v = fminf(s0, v); s0 = m;
            m = fmaxf(s1, v); v = fminf(s1, v); s1 = m;
            m = fmaxf(s2, v); v = fminf(s2, v); s2 = m;
            m = fmaxf(s3, v); v = fminf(s3, v); s3 = m;
            m = fmaxf(s4, v); v = fminf(s4, v); s4 = m;
            m = fmaxf(s5, v); v = fminf(s5, v); s5 = m;
            m = fmaxf(s6, v); v = fminf(s6, v); s6 = m;
            m = fmaxf(s7, v); v = fminf(s7, v); s7 = m;
        }
        // merge across lanes: 8 rounds of warp-argmax with multiplicity
        float mx = 0.f, thr = 0.f;
#pragma unroll
        for (int it = 0; it < 8; it++) {
            float m = s0;
#pragma unroll
            for (int o = 16; o; o >>= 1)
                m = fmaxf(m, __shfl_xor_sync(0xffffffffu, m, o));
            if (it == 0) mx  = m;
            if (it == 7) thr = m;
            unsigned msk = __ballot_sync(0xffffffffu, s0 == m);
            if (lane == (__ffs(msk) - 1)) {     // consume one instance
                s0 = s1; s1 = s2; s2 = s3; s3 = s4;
                s4 = s5; s5 = s6; s6 = s7; s7 = -CUDART_INF_F;
            }
        }

        // denominator over kept (>= thr)
        float ps = 0.f;
#pragma unroll
        for (int tt = 0; tt < 25; tt++) {
            int j = tt * 32 + lane;
            if (j < NF) {
                float v = sim[r][j];
                if (v >= thr) ps += expf(v - mx);
            }
        }
#pragma unroll
        for (int o = 16; o; o >>= 1)
            ps += __shfl_xor_sync(0xffffffffu, ps, o);
        float inv = 1.0f / ps;

        // compact kept (j, weight) deterministically
        int base = 0;
#pragma unroll
        for (int tt = 0; tt < 25; tt++) {
            int j = tt * 32 + lane;
            bool keep = (j < NF) && (sim[r][j] >= thr);
            unsigned m2 = __ballot_sync(0xffffffffu, keep);
            if (keep) {
                int pos = base + __popc(m2 & ((1u << lane) - 1u));
                if (pos < 64) {
                    kj[r][pos] = j;
                    kw[r][pos] = expf(sim[r][j] - mx) * inv;
                }
            }
            base += __popc(m2);
        }
        int nk = min(base, 64);
        __syncwarp();

        // gather: lane owns columns 2*lane, 2*lane+1
        float2 vv = *(const float2*)(vbase + (size_t)row * HD_ + 2 * lane);
        float a0 = vv.x, a1 = vv.y;
        for (int kk = 0; kk < nk; kk++) {
            int jx = kj[r][kk];
            float w = kw[r][kk];
            float2 rv = *(const float2*)(rep + (size_t)jx * HD_ + 2 * lane);
            a0 += w * rv.x;
            a1 += w * rv.y;
        }
        *(float2*)(g_vsum + ((size_t)(b * H_ + h) * P_ + row) * HD_ + 2 * lane)
            = make_float2(a0, a1);
    }
}

// ---------------------------------------------------------------------------
// Kernel 4: attention: softmax(q k^T * 0.125) @ vsum -> out (B,P,D).
// Block = PT=8 rows of one (b, h); warp-per-row softmax.
// ---------------------------------------------------------------------------
__global__ __launch_bounds__(256) void k_attn(float* __restrict__ out)
{
    int bid = blockIdx.x;
    int t  = bid % NT;
    int h  = (bid / NT) % H_;
    int b  = bid / (NT * H_);
    int p0 = t * PT;
    int tid = threadIdx.x;
    int lane = tid & 31, warp = tid >> 5;

    __shared__ float4 qp4[4][32];                    // q row-pair tile
    __shared__ __align__(16) float2 probp[4][198];   // prob row pairs (padded)
    __shared__ float  s_inv[PT];
    __shared__ float  part[4][PT][HD_];

    const float* qbase = g_qh + (size_t)(b * H_ + h) * P_ * HD_;
    for (int i = tid; i < 4 * 32; i += 256) {
        int pr = i >> 5, c2 = i & 31;
        int c = 2 * c2;
        int r0 = p0 + 2 * pr;
        float a0 = (r0     < P_) ? qbase[(size_t)r0 * HD_ + c]           : 0.f;
        float b0 = (r0 + 1 < P_) ? qbase[(size_t)(r0 + 1) * HD_ + c]     : 0.f;
        float a1 = (r0     < P_) ? qbase[(size_t)r0 * HD_ + c + 1]       : 0.f;
        float b1 = (r0 + 1 < P_) ? qbase[(size_t)(r0 + 1) * HD_ + c + 1] : 0.f;
        qp4[pr][c2] = make_float4(a0, b0, a1, b1);
    }
    __syncthreads();

    // Phase A: logits, 2 j per thread
    const float* kb = g_kh + (size_t)(b * H_ + h) * P_ * HD_;
    for (int jb = tid * 2; jb < P_; jb += 512) {
        int j0 = jb;
        int j1 = jb + 1;
        bool hv1 = (j1 < P_);
        const float4* k40 = (const float4*)(kb + (size_t)j0 * HD_);
        const float4* k41 = (const float4*)(kb + (size_t)(hv1 ? j1 : j0) * HD_);
        ull a0[4], a1[4];
#pragma unroll
        for (int pr = 0; pr < 4; pr++) { a0[pr] = 0ull; a1[pr] = 0ull; }
#pragma unroll 4
        for (int c4 = 0; c4 < 16; c4++) {
            float4 kk0 = __ldg(k40 + c4);
            float4 kk1 = __ldg(k41 + c4);
#pragma unroll
            for (int qp = 0; qp < 2; qp++) {
                int c2 = 2 * c4 + qp;
                float4 vv0 = qp4[0][c2];
                float4 vv1 = qp4[1][c2];
                float4 vv2 = qp4[2][c2];
                float4 vv3 = qp4[3][c2];
                ull v0a = lo2(vv0), v0b = hi2(vv0);
                ull v1a = lo2(vv1), v1b = hi2(vv1);
                ull v2a = lo2(vv2), v2b = hi2(vv2);
                ull v3a = lo2(vv3), v3b = hi2(vv3);
                ull pa, pb;
                float x0 = f4c(kk0, 2 * qp), y0 = f4c(kk0, 2 * qp + 1);
                pa = pack2(x0, x0); pb = pack2(y0, y0);
                a0[0] = fma2(pa, v0a, a0[0]); a0[0] = fma2(pb, v0b, a0[0]);
                a0[1] = fma2(pa, v1a, a0[1]); a0[1] = fma2(pb, v1b, a0[1]);
                a0[2] = fma2(pa, v2a, a0[2]); a0[2] = fma2(pb, v2b, a0[2]);
                a0[3] = fma2(pa, v3a, a0[3]); a0[3] = fma2(pb, v3b, a0[3]);
                float x1 = f4c(kk1, 2 * qp), y1 = f4c(kk1, 2 * qp + 1);
                pa = pack2(x1, x1); pb = pack2(y1, y1);
                a1[0] = fma2(pa, v0a, a1[0]); a1[0] = fma2(pb, v0b, a1[0]);
                a1[1] = fma2(pa, v1a, a1[1]); a1[1] = fma2(pb, v1b, a1[1]);
                a1[2] = fma2(pa, v2a, a1[2]); a1[2] = fma2(pb, v2b, a1[2]);
                a1[3] = fma2(pa, v3a, a1[3]); a1[3] = fma2(pb, v3b, a1[3]);
            }
        }
#pragma unroll
        for (int pr = 0; pr < 4; pr++) {
            float x, y;
            unpack2(a0[pr], x, y);
            probp[pr][j0] = make_float2(x * 0.125f, y * 0.125f);
        }
        if (hv1) {
#pragma unroll
            for (int pr = 0; pr < 4; pr++) {
                float x, y;
                unpack2(a1[pr], x, y);
                probp[pr][j1] = make_float2(x * 0.125f, y * 0.125f);
            }
        }
    }
    __syncthreads();

    // Phase B: warp-per-row softmax (leaves un-normalized exp; 1/sum in s_inv)
    int r = warp;
    if (p0 + r < P_) {
        int pr = r >> 1, comp = r & 1;
        float vals[7];
        float vmax = -CUDART_INF_F;
#pragma unroll
        for (int tt = 0; tt < 7; tt++) {
            int j = tt * 32 + lane;
            float x = -CUDART_INF_F;
            if (j < P_) x = ((const float*)&probp[pr][j])[comp];
            vals[tt] = x;
            vmax = fmaxf(vmax, x);
        }
#pragma unroll
        for (int o = 16; o; o >>= 1)
            vmax = fmaxf(vmax, __shfl_xor_sync(0xffffffffu, vmax, o));
        float ps = 0.f;
#pragma unroll
        for (int tt = 0; tt < 7; tt++) {
            int j = tt * 32 + lane;
            if (j < P_) {
                float e = expf(vals[tt] - vmax);
                ps += e;
                ((float*)&probp[pr][j])[comp] = e;
            }
        }
#pragma unroll
        for (int o = 16; o; o >>= 1)
            ps += __shfl_xor_sync(0xffffffffu, ps, o);
        if (lane == 0) s_inv[r] = 1.0f / ps;
    }
    __syncthreads();

    // Phase C: AV with contiguous j-range per group; probp read as LDS.128.
    {
        int g = tid >> 6, c = tid & 63;
        int jlo = g * 50;
        int jhi = min(jlo + 50, P_);
        ull acc2[4] = {0ull, 0ull, 0ull, 0ull};
        const float* vb = g_vsum + (size_t)(b * H_ + h) * P_ * HD_;
        int j = jlo;
        for (; j + 1 < jhi; j += 2) {
            float va = __ldg(vb + (size_t)j * HD_ + c);
            float vbv = __ldg(vb + (size_t)(j + 1) * HD_ + c);
            ull v2a = pack2(va, va);
            ull v2b = pack2(vbv, vbv);
#pragma unroll
            for (int pr = 0; pr < 4; pr++) {
                float4 wp = *(const float4*)&probp[pr][j];   // (j, j+1) pairs
                acc2[pr] = fma2(lo2(wp), v2a, acc2[pr]);
                acc2[pr] = fma2(hi2(wp), v2b, acc2[pr]);
            }
        }
        if (j < jhi) {
            float va = __ldg(vb + (size_t)j * HD_ + c);
            ull v2a = pack2(va, va);
#pragma unroll
            for (int pr = 0; pr < 4; pr++) {
                ull w = *(const ull*)&probp[pr][j];
                acc2[pr] = fma2(w, v2a, acc2[pr]);
            }
        }
#pragma unroll
        for (int pr = 0; pr < 4; pr++) {
            float x, y;
            unpack2(acc2[pr], x, y);
            part[g][2 * pr + 0][c] = x;
            part[g][2 * pr + 1][c] = y;
        }
    }
    __syncthreads();

    // epilogue: normalize + write
    for (int rr = tid >> 6; rr < PT; rr += 4) {
        int cc = tid & 63;
        if (p0 + rr < P_) {
            float s = part[0][rr][cc] + part[1][rr][cc]
                    + part[2][rr][cc] + part[3][rr][cc];
            out[((size_t)b * P_ + p0 + rr) * D_ + h * HD_ + cc] = s * s_inv[rr];
        }
    }
}

// ---------------------------------------------------------------------------
extern "C" void kernel_launch(void* const* d_in, const int* in_sizes, int n_in,
                              void* d_out, int out_size)
{
    const float* q   = (const float*)d_in[0];
    const float* k   = (const float*)d_in[1];
    const float* v   = (const float*)d_in[2];
    const float* wq  = (const float*)d_in[3];
    const float* wk  = (const float*)d_in[4];
    const float* wv  = (const float*)d_in[5];
    const int* idxs  = (const int*)d_in[6];
    float* out = (float*)d_out;

    k_rms<<<B_ * P_, 256>>>(q, k, v, wq, wk, wv);
    k_rep<<<(H_ * NF * HD_ + 255) / 256, 256>>>(idxs);
    k_align<<<B_ * H_ * NT, 256>>>();
    k_attn<<<B_ * H_ * NT, 256>>>(out);
}

// round 7
// speedup vs baseline: 2.8743x; 1.1572x over previous
#include <cuda_runtime.h>
#include <math_constants.h>

typedef unsigned long long ull;

namespace {
constexpr int B_   = 32;
constexpr int P_   = 197;
constexpr int D_   = 768;
constexpr int H_   = 12;
constexpr int HD_  = 64;
constexpr int PPR  = 49;    // rep tokens per reference sample
constexpr int NREF = 16;    // int(B * 0.5)
constexpr int NF   = 784;   // NREF * PPR
constexpr int PT   = 12;    // rows per block in k_align
constexpr int NT   = (P_ + PT - 1) / PT;   // 17
constexpr int PTA  = 8;     // rows per block in k_attn
constexpr int NTA  = (P_ + PTA - 1) / PTA; // 25
constexpr float NEGF = -1e30f;
}

// scratch (device globals; no allocation allowed)
__device__ float g_qh  [B_ * H_ * P_ * HD_];
__device__ float g_khT [B_ * H_ * HD_ * P_];   // [b][h][c][p]
__device__ float g_vh  [B_ * H_ * P_ * HD_];
__device__ float g_vsum[B_ * H_ * P_ * HD_];
__device__ float g_rep [H_ * NF * HD_];        // [h][j][c]
__device__ float g_repT[H_ * HD_ * NF];        // [h][c][j]

// ---- packed f32x2 helpers (sm_103a) --------------------------------------
__device__ __forceinline__ ull pack2(float x, float y) {
    ull r; asm("mov.b64 %0, {%1, %2};" : "=l"(r) : "f"(x), "f"(y)); return r;
}
__device__ __forceinline__ ull fma2(ull a, ull b, ull c) {
    ull d; asm("fma.rn.f32x2 %0, %1, %2, %3;" : "=l"(d) : "l"(a), "l"(b), "l"(c));
    return d;
}
__device__ __forceinline__ void unpack2(ull p, float& x, float& y) {
    asm("mov.b64 {%0, %1}, %2;" : "=f"(x), "=f"(y) : "l"(p));
}

// ---------------------------------------------------------------------------
// Kernel 1: RMSNorm (over D=768) + head split. K goes out transposed.
// ---------------------------------------------------------------------------
__global__ __launch_bounds__(256) void k_rms(
    const float* __restrict__ q, const float* __restrict__ k,
    const float* __restrict__ v, const float* __restrict__ wq,
    const float* __restrict__ wk, const float* __restrict__ wv)
{
    int bp = blockIdx.x;
    int b = bp / P_;
    int p = bp % P_;
    int tid = threadIdx.x;
    int lane = tid & 31, warp = tid >> 5;
    size_t off = (size_t)bp * D_;

    float xq[3], xk[3], xv[3];
    float sq = 0.f, sk = 0.f, sv = 0.f;
#pragma unroll
    for (int i = 0; i < 3; i++) {
        int j = tid + i * 256;
        xq[i] = q[off + j]; sq += xq[i] * xq[i];
        xk[i] = k[off + j]; sk += xk[i] * xk[i];
        xv[i] = v[off + j]; sv += xv[i] * xv[i];
    }
#pragma unroll
    for (int o = 16; o; o >>= 1) {
        sq += __shfl_xor_sync(0xffffffffu, sq, o);
        sk += __shfl_xor_sync(0xffffffffu, sk, o);
        sv += __shfl_xor_sync(0xffffffffu, sv, o);
    }
    __shared__ float s_q[8], s_k[8], s_v[8];
    if (lane == 0) { s_q[warp] = sq; s_k[warp] = sk; s_v[warp] = sv; }
    __syncthreads();
    float tq = 0.f, tk = 0.f, tv = 0.f;
#pragma unroll
    for (int w = 0; w < 8; w++) { tq += s_q[w]; tk += s_k[w]; tv += s_v[w]; }
    float rq = rsqrtf(tq * (1.0f / D_) + 1e-6f);
    float rk = rsqrtf(tk * (1.0f / D_) + 1e-6f);
    float rv = rsqrtf(tv * (1.0f / D_) + 1e-6f);

#pragma unroll
    for (int i = 0; i < 3; i++) {
        int j = tid + i * 256;
        int h = j >> 6, c = j & 63;
        int di = ((b * H_ + h) * P_ + p) * HD_ + c;
        g_qh[di] = xq[i] * rq * wq[j];
        g_vh[di] = xv[i] * rv * wv[j];
        g_khT[((b * H_ + h) * HD_ + c) * P_ + p] = xk[i] * rk * wk[j];
    }
}

// ---------------------------------------------------------------------------
// Kernel 2: gather representative tokens (row-major + transposed).
// ---------------------------------------------------------------------------
__global__ __launch_bounds__(256) void k_rep(const int* __restrict__ idxs)
{
    int t = blockIdx.x * 256 + threadIdx.x;
    if (t >= H_ * NF * HD_) return;
    int c  = t & 63;
    int rj = (t >> 6) % NF;
    int h  = t / (NF * HD_);
    int nn = rj / PPR;
    int j  = rj % PPR;
    int sp = idxs[j];
    float val = g_vh[((nn * H_ + h) * P_ + sp) * HD_ + c];
    g_rep[t] = val;
    g_repT[(h * HD_ + c) * NF + rj] = val;
}

// ---------------------------------------------------------------------------
// Kernel 3: sim (coalesced repT) + warp top-8 + sparse softmax + v_aligned.
// Block = 256 threads, PT=12 rows of one (b, h).
// ---------------------------------------------------------------------------
__global__ __launch_bounds__(256) void k_align()
{
    int bid = blockIdx.x;
    int t  = bid % NT;
    int h  = (bid / NT) % H_;
    int b  = bid / (NT * H_);
    int p0 = t * PT;
    int tid = threadIdx.x;
    int lane = tid & 31, warp = tid >> 5;

    __shared__ float2 vp2[6][HD_];      // row-pair (2pr, 2pr+1) per column
    __shared__ float  sim[PT][NF];
    __shared__ int    kj[PT][64];
    __shared__ float  kw[PT][64];

    const float* vbase = g_vh + (size_t)(b * H_ + h) * P_ * HD_;

    // load row pairs
    for (int i = tid; i < 6 * HD_; i += 256) {
        int pr = i >> 6, c = i & 63;
        int r0 = p0 + 2 * pr;
        float a = (r0     < P_) ? vbase[(size_t)r0 * HD_ + c]       : 0.f;
        float d = (r0 + 1 < P_) ? vbase[(size_t)(r0 + 1) * HD_ + c] : 0.f;
        vp2[pr][c] = make_float2(a, d);
    }
    __syncthreads();

    const float* repT = g_repT + (size_t)h * HD_ * NF;
    int mlo = b * PPR;
    bool hasmask = (b < NREF);

    // Phase 1: 196 threads x 4 consecutive j, coalesced LDG.128 from repT.
    if (tid < 196) {
        int jb = tid * 4;
        ull acc[4][6];   // [jj][pr]
#pragma unroll
        for (int jj = 0; jj < 4; jj++)
#pragma unroll
            for (int pr = 0; pr < 6; pr++) acc[jj][pr] = 0ull;

#pragma unroll 4
        for (int c = 0; c < HD_; c++) {
            float4 rr = __ldg((const float4*)(repT + (size_t)c * NF + jb));
            ull s0 = pack2(rr.x, rr.x);
            ull s1 = pack2(rr.y, rr.y);
            ull s2 = pack2(rr.z, rr.z);
            ull s3 = pack2(rr.w, rr.w);
#pragma unroll
            for (int pr = 0; pr < 6; pr++) {
                ull vpair = *(const ull*)&vp2[pr][c];   // broadcast LDS.64
                acc[0][pr] = fma2(s0, vpair, acc[0][pr]);
                acc[1][pr] = fma2(s1, vpair, acc[1][pr]);
                acc[2][pr] = fma2(s2, vpair, acc[2][pr]);
                acc[3][pr] = fma2(s3, vpair, acc[3][pr]);
            }
        }
#pragma unroll
        for (int jj = 0; jj < 4; jj++) {
            int j = jb + jj;
            bool selfm = hasmask && (j >= mlo) && (j < mlo + PPR);
#pragma unroll
            for (int pr = 0; pr < 6; pr++) {
                float x, y;
                unpack2(acc[jj][pr], x, y);
                sim[2 * pr + 0][j] = selfm ? NEGF : x;
                sim[2 * pr + 1][j] = selfm ? NEGF : y;
            }
        }
    }
    __syncthreads();

    const float* rep = g_rep + (size_t)h * NF * HD_;

    // Phases 2-3: warp-per-row (each warp handles rows warp, warp+8).
    for (int r = warp; r < PT; r += 8) {
        int row = p0 + r;
        if (row >= P_) break;

        // lane-local sorted top-8 over this lane's 25 entries
        float s0 = -CUDART_INF_F, s1 = s0, s2 = s0, s3 = s0,
              s4 = s0, s5 = s0, s6 = s0, s7 = s0;
#pragma unroll
        for (int tt = 0; tt < 25; tt++) {
            int j = tt * 32 + lane;
            float v = (j < NF) ? sim[r][j] : -CUDART_INF_F;
            float m;
            m = fmaxf(s0, v); v = fminf(s0, v); s0 = m;
            m = fmaxf(s1, v); v = fminf(s1, v); s1 = m;
            m = fmaxf(s2, v); v = fminf(s2, v); s2 = m;
            m = fmaxf(s3, v); v = fminf(s3, v); s3 = m;
            m = fmaxf(s4, v); v = fminf(s4, v); s4 = m;
            m = fmaxf(s5, v); v = fminf(s5, v); s5 = m;
            m = fmaxf(s6, v); v = fminf(s6, v); s6 = m;
            m = fmaxf(s7, v); v = fminf(s7, v); s7 = m;
        }
        // merge across lanes: 8 rounds of warp-max with multiplicity
        float mx = 0.f, thr = 0.f;
#pragma unroll
        for (int it = 0; it < 8; it++) {
            float m = s0;
#pragma unroll
            for (int o = 16; o; o >>= 1)
                m = fmaxf(m, __shfl_xor_sync(0xffffffffu, m, o));
            if (it == 0) mx  = m;
            if (it == 7) thr = m;
            unsigned msk = __ballot_sync(0xffffffffu, s0 == m);
            if (lane == (__ffs(msk) - 1)) {     // consume one instance
                s0 = s1; s1 = s2; s2 = s3; s3 = s4;
                s4 = s5; s5 = s6; s6 = s7; s7 = -CUDART_INF_F;
            }
        }

        // denominator over kept (>= thr)
        float ps = 0.f;
#pragma unroll
        for (int tt = 0; tt < 25; tt++) {
            int j = tt * 32 + lane;
            if (j < NF) {
                float v = sim[r][j];
                if (v >= thr) ps += expf(v - mx);
            }
        }
#pragma unroll
        for (int o = 16; o; o >>= 1)
            ps += __shfl_xor_sync(0xffffffffu, ps, o);
        float inv = 1.0f / ps;

        // compact kept (j, weight) deterministically
        int base = 0;
#pragma unroll
        for (int tt = 0; tt < 25; tt++) {
            int j = tt * 32 + lane;
            bool keep = (j < NF) && (sim[r][j] >= thr);
            unsigned m2 = __ballot_sync(0xffffffffu, keep);
            if (keep) {
                int pos = base + __popc(m2 & ((1u << lane) - 1u));
                if (pos < 64) {
                    kj[r][pos] = j;
                    kw[r][pos] = expf(sim[r][j] - mx) * inv;
                }
            }
            base += __popc(m2);
        }
        int nk = min(base, 64);
        __syncwarp();

        // gather: lane owns columns 2*lane, 2*lane+1
        float2 vv = *(const float2*)(vbase + (size_t)row * HD_ + 2 * lane);
        float a0 = vv.x, a1 = vv.y;
        for (int kk = 0; kk < nk; kk++) {
            int jx = kj[r][kk];
            float w = kw[r][kk];
            float2 rv = *(const float2*)(rep + (size_t)jx * HD_ + 2 * lane);
            a0 += w * rv.x;
            a1 += w * rv.y;
        }
        *(float2*)(g_vsum + ((size_t)(b * H_ + h) * P_ + row) * HD_ + 2 * lane)
            = make_float2(a0, a1);
        __syncwarp();
    }
}

// ---------------------------------------------------------------------------
// Kernel 4: attention: softmax(q k^T * 0.125) @ vsum -> out (B,P,D).
// Block = PTA=8 rows of one (b, h); K read coalesced from g_khT.
// ---------------------------------------------------------------------------
__global__ __launch_bounds__(256) void k_attn(float* __restrict__ out)
{
    int bid = blockIdx.x;
    int t  = bid % NTA;
    int h  = (bid / NTA) % H_;
    int b  = bid / (NTA * H_);
    int p0 = t * PTA;
    int tid = threadIdx.x;
    int lane = tid & 31, warp = tid >> 5;

    __shared__ float2 qp2[4][HD_];                   // q row pairs
    __shared__ __align__(16) float2 probp[4][198];   // prob row pairs (padded)
    __shared__ float  s_inv[PTA];
    __shared__ float  part[4][PTA][HD_];

    const float* qbase = g_qh + (size_t)(b * H_ + h) * P_ * HD_;
    for (int i = tid; i < 4 * HD_; i += 256) {
        int pr = i >> 6, c = i & 63;
        int r0 = p0 + 2 * pr;
        float a = (r0     < P_) ? qbase[(size_t)r0 * HD_ + c]       : 0.f;
        float d = (r0 + 1 < P_) ? qbase[(size_t)(r0 + 1) * HD_ + c] : 0.f;
        qp2[pr][c] = make_float2(a, d);
    }
    __syncthreads();

    // Phase A: logits; thread j = tid (<197), coalesced LDG.32 from khT.
    if (tid < P_) {
        int j = tid;
        const float* khT = g_khT + (size_t)(b * H_ + h) * HD_ * P_;
        ull a[4] = {0ull, 0ull, 0ull, 0ull};
#pragma unroll 4
        for (int c = 0; c < HD_; c++) {
            float kv = __ldg(khT + (size_t)c * P_ + j);
            ull s = pack2(kv, kv);
#pragma unroll
            for (int pr = 0; pr < 4; pr++) {
                ull qpair = *(const ull*)&qp2[pr][c];
                a[pr] = fma2(s, qpair, a[pr]);
            }
        }
#pragma unroll
        for (int pr = 0; pr < 4; pr++) {
            float x, y;
            unpack2(a[pr], x, y);
            probp[pr][j] = make_float2(x * 0.125f, y * 0.125f);
        }
    }
    __syncthreads();

    // Phase B: warp-per-row softmax (leaves un-normalized exp; 1/sum in s_inv)
    int r = warp;
    if (p0 + r < P_) {
        int pr = r >> 1, comp = r & 1;
        float vals[7];
        float vmax = -CUDART_INF_F;
#pragma unroll
        for (int tt = 0; tt < 7; tt++) {
            int j = tt * 32 + lane;
            float x = -CUDART_INF_F;
            if (j < P_) x = ((const float*)&probp[pr][j])[comp];
            vals[tt] = x;
            vmax = fmaxf(vmax, x);
        }
#pragma unroll
        for (int o = 16; o; o >>= 1)
            vmax = fmaxf(vmax, __shfl_xor_sync(0xffffffffu, vmax, o));
        float ps = 0.f;
#pragma unroll
        for (int tt = 0; tt < 7; tt++) {
            int j = tt * 32 + lane;
            if (j < P_) {
                float e = expf(vals[tt] - vmax);
                ps += e;
                ((float*)&probp[pr][j])[comp] = e;
            }
        }
#pragma unroll
        for (int o = 16; o; o >>= 1)
            ps += __shfl_xor_sync(0xffffffffu, ps, o);
        if (lane == 0) s_inv[r] = 1.0f / ps;
    }
    __syncthreads();

    // Phase C: AV with contiguous j-range per group; probp read as LDS.128.
    {
        int g = tid >> 6, c = tid & 63;
        int jlo = g * 50;
        int jhi = min(jlo + 50, P_);
        ull acc2[4] = {0ull, 0ull, 0ull, 0ull};
        const float* vb = g_vsum + (size_t)(b * H_ + h) * P_ * HD_;
        int j = jlo;
        for (; j + 1 < jhi; j += 2) {
            float va  = __ldg(vb + (size_t)j * HD_ + c);
            float vbv = __ldg(vb + (size_t)(j + 1) * HD_ + c);
            ull v2a = pack2(va, va);
            ull v2b = pack2(vbv, vbv);
#pragma unroll
            for (int pr = 0; pr < 4; pr++) {
                float4 wp = *(const float4*)&probp[pr][j];   // (j, j+1) pairs
                ull wlo, whi;
                asm("mov.b64 %0, {%2, %3}; mov.b64 %1, {%4, %5};"
                    : "=l"(wlo), "=l"(whi)
                    : "f"(wp.x), "f"(wp.y), "f"(wp.z), "f"(wp.w));
                acc2[pr] = fma2(wlo, v2a, acc2[pr]);
                acc2[pr] = fma2(whi, v2b, acc2[pr]);
            }
        }
        if (j < jhi) {
            float va = __ldg(vb + (size_t)j * HD_ + c);
            ull v2a = pack2(va, va);
#pragma unroll
            for (int pr = 0; pr < 4; pr++) {
                ull w = *(const ull*)&probp[pr][j];
                acc2[pr] = fma2(w, v2a, acc2[pr]);
            }
        }
#pragma unroll
        for (int pr = 0; pr < 4; pr++) {
            float x, y;
            unpack2(acc2[pr], x, y);
            part[g][2 * pr + 0][c] = x;
            part[g][2 * pr + 1][c] = y;
        }
    }
    __syncthreads();

    // epilogue: normalize + write
    for (int rr = tid >> 6; rr < PTA; rr += 4) {
        int cc = tid & 63;
        if (p0 + rr < P_) {
            float s = part[0][rr][cc] + part[1][rr][cc]
                    + part[2][rr][cc] + part[3][rr][cc];
            out[((size_t)b * P_ + p0 + rr) * D_ + h * HD_ + cc] = s * s_inv[rr];
        }
    }
}

// ---------------------------------------------------------------------------
extern "C" void kernel_launch(void* const* d_in, const int* in_sizes, int n_in,
                              void* d_out, int out_size)
{
    const float* q   = (const float*)d_in[0];
    const float* k   = (const float*)d_in[1];
    const float* v   = (const float*)d_in[2];
    const float* wq  = (const float*)d_in[3];
    const float* wk  = (const float*)d_in[4];
    const float* wv  = (const float*)d_in[5];
    const int* idxs  = (const int*)d_in[6];
    float* out = (float*)d_out;

    k_rms<<<B_ * P_, 256>>>(q, k, v, wq, wk, wv);
    k_rep<<<(H_ * NF * HD_ + 255) / 256, 256>>>(idxs);
    k_align<<<B_ * H_ * NT, 256>>>();
    k_attn<<<B_ * H_ * NTA, 256>>>(out);
}